// round 2
// baseline (speedup 1.0000x reference)
#include <cuda_runtime.h>

#define BOX 256
#define KS 9
#define NP 20000
#define NB 16
#define NN 32
#define NL 3
#define LATENT 8

#define IMG_SIZE (NB*BOX*BOX)            /* 1048576 */
#define OFF_PD   (IMG_SIZE)              /* 1048576 */
#define OFF_RES  (OFF_PD + NB*NP*3)      /* 2008576 */
#define OFF_AC   (OFF_RES + NB*NP*3)     /* 2968576 */

__global__ void zero_img_kernel(float4* out) {
    int i = blockIdx.x * blockDim.x + threadIdx.x;
    if (i < IMG_SIZE / 4) out[i] = make_float4(0.f, 0.f, 0.f, 0.f);
}

__global__ void __launch_bounds__(256) fused_decoder_kernel(
    const float* __restrict__ z,          // [16,8]
    const float* __restrict__ r,          // [16,3,3]
    const float* __restrict__ pos,        // [20000,3]
    const float* __restrict__ amp,        // [1]
    const float* __restrict__ linamp1_W,  // [32,4]
    const float* __restrict__ ampblock_W, // [3,32,32]
    const float* __restrict__ ampblock_b, // [3,32]
    const float* __restrict__ linamp2_W,  // [1,32]
    const float* __restrict__ linamp2_b,  // [1]
    const float* __restrict__ lin0_W,     // [32,10]
    const float* __restrict__ deform_W,   // [3,32,32]
    const float* __restrict__ deform_b,   // [3,32]
    const float* __restrict__ lin1a_W,    // [3,32]
    const float* __restrict__ lin1b_W,    // [3,3]
    const float* __restrict__ k2,         // [9,9]
    const int*   __restrict__ dptr,       // [1]
    float* __restrict__ out)
{
    __shared__ __align__(16) float s_ab_W[NL*NN*NN];
    __shared__ __align__(16) float s_df_W[NL*NN*NN];
    __shared__ float s_ab_b[NL*NN];
    __shared__ float s_df_b[NL*NN];
    __shared__ float s_la1[NN*4];
    __shared__ float s_la2[NN];
    __shared__ float s_l0[NN*10];
    __shared__ float s_l1a[3*NN];
    __shared__ float s_l1b[9];
    __shared__ float s_k2[81];
    __shared__ float s_z[NB*LATENT];
    __shared__ float s_r[NB*9];
    __shared__ float s_la2b, s_amp;

    int tid = threadIdx.x;
    for (int i = tid; i < NL*NN*NN; i += blockDim.x) { s_ab_W[i] = ampblock_W[i]; s_df_W[i] = deform_W[i]; }
    for (int i = tid; i < NL*NN; i += blockDim.x)    { s_ab_b[i] = ampblock_b[i]; s_df_b[i] = deform_b[i]; }
    for (int i = tid; i < NN*4; i += blockDim.x)     s_la1[i] = linamp1_W[i];
    for (int i = tid; i < NN; i += blockDim.x)       s_la2[i] = linamp2_W[i];
    for (int i = tid; i < NN*10; i += blockDim.x)    s_l0[i]  = lin0_W[i];
    for (int i = tid; i < 3*NN; i += blockDim.x)     s_l1a[i] = lin1a_W[i];
    for (int i = tid; i < 9; i += blockDim.x)        s_l1b[i] = lin1b_W[i];
    for (int i = tid; i < 81; i += blockDim.x)       s_k2[i]  = k2[i];
    for (int i = tid; i < NB*LATENT; i += blockDim.x) s_z[i]  = z[i];
    for (int i = tid; i < NB*9; i += blockDim.x)      s_r[i]  = r[i];
    if (tid == 0) { s_la2b = linamp2_b[0]; s_amp = amp[0]; }
    __syncthreads();

    int idx = blockIdx.x * blockDim.x + tid;
    if (idx >= NB*NP) return;
    int p = idx % NP;
    int b = idx / NP;
    int d = *dptr;

    float px = pos[3*p + 0];
    float py = pos[3*p + 1];
    float pz = pos[3*p + 2];

    // ------------------ amplitude head ------------------
    float x[NN];
    {
        float i3 = s_z[b*LATENT + 7];
        #pragma unroll
        for (int i = 0; i < NN; i++) {
            const float4 w = *(const float4*)&s_la1[i*4];
            x[i] = w.x*px + w.y*py + w.z*pz + w.w*i3;
        }
    }
    #pragma unroll
    for (int l = 0; l < NL; l++) {
        float y[NN];
        #pragma unroll
        for (int i = 0; i < NN; i++) {
            const float4* wr = (const float4*)&s_ab_W[(l*NN + i)*NN];
            float acc = s_ab_b[l*NN + i];
            #pragma unroll
            for (int j = 0; j < NN/4; j++) {
                float4 w = wr[j];
                acc += w.x*x[4*j] + w.y*x[4*j+1] + w.z*x[4*j+2] + w.w*x[4*j+3];
            }
            y[i] = fmaxf(acc, 0.f) + x[i];
        }
        #pragma unroll
        for (int i = 0; i < NN; i++) x[i] = y[i];
    }
    float sacc = s_la2b;
    #pragma unroll
    for (int i = 0; i < NN; i++) sacc += x[i]*s_la2[i];
    float amp_corr = 1.f / (1.f + expf(-sacc));

    // ------------------ deform head ------------------
    float res0 = 0.f, res1 = 0.f, res2 = 0.f;
    if (d > 0) {
        float in10[10];
        in10[0] = px; in10[1] = py; in10[2] = pz;
        #pragma unroll
        for (int j = 0; j < LATENT-1; j++) in10[3+j] = s_z[b*LATENT + j];
        #pragma unroll
        for (int i = 0; i < NN; i++) {
            float acc = 0.f;
            #pragma unroll
            for (int j = 0; j < 10; j++) acc += s_l0[i*10 + j]*in10[j];
            x[i] = acc;
        }
        #pragma unroll
        for (int l = 0; l < NL; l++) {
            float y[NN];
            #pragma unroll
            for (int i = 0; i < NN; i++) {
                const float4* wr = (const float4*)&s_df_W[(l*NN + i)*NN];
                float acc = s_df_b[l*NN + i];
                #pragma unroll
                for (int j = 0; j < NN/4; j++) {
                    float4 w = wr[j];
                    acc += w.x*x[4*j] + w.y*x[4*j+1] + w.z*x[4*j+2] + w.w*x[4*j+3];
                }
                y[i] = fmaxf(acc, 0.f) + x[i];
            }
            #pragma unroll
            for (int i = 0; i < NN; i++) x[i] = y[i];
        }
        float t0 = 0.f, t1 = 0.f, t2 = 0.f;
        #pragma unroll
        for (int j = 0; j < NN; j++) {
            t0 += x[j]*s_l1a[0*NN + j];
            t1 += x[j]*s_l1a[1*NN + j];
            t2 += x[j]*s_l1a[2*NN + j];
        }
        t0 = tanhf(t0); t1 = tanhf(t1); t2 = tanhf(t2);
        res0 = t0*s_l1b[0] + t1*s_l1b[1] + t2*s_l1b[2];
        res1 = t0*s_l1b[3] + t1*s_l1b[4] + t2*s_l1b[5];
        res2 = t0*s_l1b[6] + t1*s_l1b[7] + t2*s_l1b[8];
    }
    float pd0 = px + res0;
    float pd1 = py + res1;
    float pd2 = pz + res2;

    // ------------------ outputs (pos_def, res, amp_corr) ------------------
    out[OFF_AC + idx] = amp_corr;
    out[OFF_RES + 3*idx + 0] = res0;
    out[OFF_RES + 3*idx + 1] = res1;
    out[OFF_RES + 3*idx + 2] = res2;
    out[OFF_PD + 3*idx + 0] = pd0;
    out[OFF_PD + 3*idx + 1] = pd1;
    out[OFF_PD + 3*idx + 2] = pd2;

    // ------------------ project + splat ------------------
    const float* rb = &s_r[b*9];
    float proj0 = rb[0]*pd0 + rb[1]*pd1 + rb[2]*pd2;
    float proj1 = rb[3]*pd0 + rb[4]*pd1 + rb[5]*pd2;

    float A = s_amp * amp_corr;
    float pix_x = (proj0 + 0.5f) * (float)(BOX - 1);
    float pix_y = (proj1 + 0.5f) * (float)(BOX - 1);
    int cx = (int)rintf(pix_x);   // round-half-even, matches jnp.round
    int cy = (int)rintf(pix_y);

    float* img = out + (size_t)b * BOX * BOX;
    #pragma unroll
    for (int jy = 0; jy < KS; jy++) {
        int yy = cy + jy - KS/2;
        if (yy < 0 || yy >= BOX) continue;
        float* row = img + yy*BOX;
        #pragma unroll
        for (int jx = 0; jx < KS; jx++) {
            int xx = cx + jx - KS/2;
            if (xx < 0 || xx >= BOX) continue;
            atomicAdd(&row[xx], A * s_k2[jy*KS + jx]);
        }
    }
}

extern "C" void kernel_launch(void* const* d_in, const int* in_sizes, int n_in,
                              void* d_out, int out_size)
{
    const float* z          = (const float*)d_in[0];
    const float* r          = (const float*)d_in[1];
    const float* pos        = (const float*)d_in[2];
    const float* amp        = (const float*)d_in[3];
    const float* linamp1_W  = (const float*)d_in[4];
    const float* ampblock_W = (const float*)d_in[5];
    const float* ampblock_b = (const float*)d_in[6];
    const float* linamp2_W  = (const float*)d_in[7];
    const float* linamp2_b  = (const float*)d_in[8];
    const float* lin0_W     = (const float*)d_in[9];
    const float* deform_W   = (const float*)d_in[10];
    const float* deform_b   = (const float*)d_in[11];
    const float* lin1a_W    = (const float*)d_in[12];
    const float* lin1b_W    = (const float*)d_in[13];
    const float* k2         = (const float*)d_in[14];
    const int*   dptr       = (const int*)d_in[15];
    float* out = (float*)d_out;

    zero_img_kernel<<<IMG_SIZE/4/256, 256>>>((float4*)out);
    fused_decoder_kernel<<<(NB*NP + 255)/256, 256>>>(
        z, r, pos, amp, linamp1_W, ampblock_W, ampblock_b, linamp2_W, linamp2_b,
        lin0_W, deform_W, deform_b, lin1a_W, lin1b_W, k2, dptr, out);
}

// round 3
// speedup vs baseline: 2.3941x; 2.3941x over previous
#include <cuda_runtime.h>

#define BOX 256
#define KS 9
#define HALF (KS/2)
#define NP 20000
#define NB 16
#define NN 32
#define NL 3
#define LATENT 8

#define TROWS (BOX + KS - 1)             /* 264 padded rows */
#define IMG_SIZE (NB*BOX*BOX)            /* 1048576 */
#define OFF_PD   (IMG_SIZE)              /* 1048576 */
#define OFF_RES  (OFF_PD + NB*NP*3)      /* 2008576 */
#define OFF_AC   (OFF_RES + NB*NP*3)     /* 2968576 */

__device__ float g_tmp[NB * TROWS * BOX];   /* 4.3 MB scratch, y-padded splat buffer */

__global__ void zero_tmp_kernel(void) {
    int i = blockIdx.x * blockDim.x + threadIdx.x;
    if (i < NB*TROWS*BOX/4) ((float4*)g_tmp)[i] = make_float4(0.f, 0.f, 0.f, 0.f);
}

__global__ void __launch_bounds__(256) fused_decoder_kernel(
    const float* __restrict__ z,          // [16,8]
    const float* __restrict__ r,          // [16,3,3]
    const float* __restrict__ pos,        // [20000,3]
    const float* __restrict__ amp,        // [1]
    const float* __restrict__ linamp1_W,  // [32,4]
    const float* __restrict__ ampblock_W, // [3,32,32]
    const float* __restrict__ ampblock_b, // [3,32]
    const float* __restrict__ linamp2_W,  // [1,32]
    const float* __restrict__ linamp2_b,  // [1]
    const float* __restrict__ lin0_W,     // [32,10]
    const float* __restrict__ deform_W,   // [3,32,32]
    const float* __restrict__ deform_b,   // [3,32]
    const float* __restrict__ lin1a_W,    // [3,32]
    const float* __restrict__ lin1b_W,    // [3,3]
    const float* __restrict__ k2,         // [9,9]
    const int*   __restrict__ dptr,       // [1]
    float* __restrict__ out)
{
    __shared__ __align__(16) float s_ab_W[NL*NN*NN];
    __shared__ __align__(16) float s_df_W[NL*NN*NN];
    __shared__ float s_ab_b[NL*NN];
    __shared__ float s_df_b[NL*NN];
    __shared__ float s_la1[NN*4];
    __shared__ float s_la2[NN];
    __shared__ float s_l0[NN*10];
    __shared__ float s_l1a[3*NN];
    __shared__ float s_l1b[9];
    __shared__ float s_kx[KS];
    __shared__ float s_z[NB*LATENT];
    __shared__ float s_r[NB*9];
    __shared__ float s_la2b, s_amp;

    int tid = threadIdx.x;
    for (int i = tid; i < NL*NN*NN; i += blockDim.x) { s_ab_W[i] = ampblock_W[i]; s_df_W[i] = deform_W[i]; }
    for (int i = tid; i < NL*NN; i += blockDim.x)    { s_ab_b[i] = ampblock_b[i]; s_df_b[i] = deform_b[i]; }
    for (int i = tid; i < NN*4; i += blockDim.x)     s_la1[i] = linamp1_W[i];
    for (int i = tid; i < NN; i += blockDim.x)       s_la2[i] = linamp2_W[i];
    for (int i = tid; i < NN*10; i += blockDim.x)    s_l0[i]  = lin0_W[i];
    for (int i = tid; i < 3*NN; i += blockDim.x)     s_l1a[i] = lin1a_W[i];
    for (int i = tid; i < 9; i += blockDim.x)        s_l1b[i] = lin1b_W[i];
    for (int i = tid; i < KS; i += blockDim.x)       s_kx[i]  = k2[HALF*KS + i];   /* kx[j] = k2[4][j] */
    for (int i = tid; i < NB*LATENT; i += blockDim.x) s_z[i]  = z[i];
    for (int i = tid; i < NB*9; i += blockDim.x)      s_r[i]  = r[i];
    if (tid == 0) { s_la2b = linamp2_b[0]; s_amp = amp[0]; }
    __syncthreads();

    int idx = blockIdx.x * blockDim.x + tid;
    if (idx >= NB*NP) return;
    int p = idx % NP;
    int b = idx / NP;
    int d = *dptr;

    float px = pos[3*p + 0];
    float py = pos[3*p + 1];
    float pz = pos[3*p + 2];

    // ------------------ amplitude head ------------------
    float x[NN];
    {
        float i3 = s_z[b*LATENT + 7];
        #pragma unroll
        for (int i = 0; i < NN; i++) {
            const float4 w = *(const float4*)&s_la1[i*4];
            x[i] = w.x*px + w.y*py + w.z*pz + w.w*i3;
        }
    }
    #pragma unroll
    for (int l = 0; l < NL; l++) {
        float y[NN];
        #pragma unroll
        for (int i = 0; i < NN; i++) {
            const float4* wr = (const float4*)&s_ab_W[(l*NN + i)*NN];
            float acc = s_ab_b[l*NN + i];
            #pragma unroll
            for (int j = 0; j < NN/4; j++) {
                float4 w = wr[j];
                acc += w.x*x[4*j] + w.y*x[4*j+1] + w.z*x[4*j+2] + w.w*x[4*j+3];
            }
            y[i] = fmaxf(acc, 0.f) + x[i];
        }
        #pragma unroll
        for (int i = 0; i < NN; i++) x[i] = y[i];
    }
    float sacc = s_la2b;
    #pragma unroll
    for (int i = 0; i < NN; i++) sacc += x[i]*s_la2[i];
    float amp_corr = 1.f / (1.f + expf(-sacc));

    // ------------------ deform head ------------------
    float res0 = 0.f, res1 = 0.f, res2 = 0.f;
    if (d > 0) {
        float in10[10];
        in10[0] = px; in10[1] = py; in10[2] = pz;
        #pragma unroll
        for (int j = 0; j < LATENT-1; j++) in10[3+j] = s_z[b*LATENT + j];
        #pragma unroll
        for (int i = 0; i < NN; i++) {
            float acc = 0.f;
            #pragma unroll
            for (int j = 0; j < 10; j++) acc += s_l0[i*10 + j]*in10[j];
            x[i] = acc;
        }
        #pragma unroll
        for (int l = 0; l < NL; l++) {
            float y[NN];
            #pragma unroll
            for (int i = 0; i < NN; i++) {
                const float4* wr = (const float4*)&s_df_W[(l*NN + i)*NN];
                float acc = s_df_b[l*NN + i];
                #pragma unroll
                for (int j = 0; j < NN/4; j++) {
                    float4 w = wr[j];
                    acc += w.x*x[4*j] + w.y*x[4*j+1] + w.z*x[4*j+2] + w.w*x[4*j+3];
                }
                y[i] = fmaxf(acc, 0.f) + x[i];
            }
            #pragma unroll
            for (int i = 0; i < NN; i++) x[i] = y[i];
        }
        float t0 = 0.f, t1 = 0.f, t2 = 0.f;
        #pragma unroll
        for (int j = 0; j < NN; j++) {
            t0 += x[j]*s_l1a[0*NN + j];
            t1 += x[j]*s_l1a[1*NN + j];
            t2 += x[j]*s_l1a[2*NN + j];
        }
        t0 = tanhf(t0); t1 = tanhf(t1); t2 = tanhf(t2);
        res0 = t0*s_l1b[0] + t1*s_l1b[1] + t2*s_l1b[2];
        res1 = t0*s_l1b[3] + t1*s_l1b[4] + t2*s_l1b[5];
        res2 = t0*s_l1b[6] + t1*s_l1b[7] + t2*s_l1b[8];
    }
    float pd0 = px + res0;
    float pd1 = py + res1;
    float pd2 = pz + res2;

    // ------------------ outputs (pos_def, res, amp_corr) ------------------
    out[OFF_AC + idx] = amp_corr;
    out[OFF_RES + 3*idx + 0] = res0;
    out[OFF_RES + 3*idx + 1] = res1;
    out[OFF_RES + 3*idx + 2] = res2;
    out[OFF_PD + 3*idx + 0] = pd0;
    out[OFF_PD + 3*idx + 1] = pd1;
    out[OFF_PD + 3*idx + 2] = pd2;

    // ------------------ project + separable splat (x-pass scatter) ------------------
    const float* rb = &s_r[b*9];
    float proj0 = rb[0]*pd0 + rb[1]*pd1 + rb[2]*pd2;
    float proj1 = rb[3]*pd0 + rb[4]*pd1 + rb[5]*pd2;

    float A = s_amp * amp_corr;
    float pix_x = (proj0 + 0.5f) * (float)(BOX - 1);
    float pix_y = (proj1 + 0.5f) * (float)(BOX - 1);
    int cx = (int)rintf(pix_x);   // round-half-even, matches jnp.round
    int cy = (int)rintf(pix_y);

    // A point contributes iff some yy=cy+jy-4 is in [0,BOX): cy in [-4, BOX+3]
    if (cy >= -HALF && cy <= BOX - 1 + HALF) {
        float* trow = g_tmp + ((size_t)b * TROWS + (cy + HALF)) * BOX;
        #pragma unroll
        for (int jx = 0; jx < KS; jx++) {
            int xx = cx + jx - HALF;
            if (xx >= 0 && xx < BOX) atomicAdd(&trow[xx], A * s_kx[jx]);
        }
    }
}

// Dense y-convolution: img[b][y][x] = sum_jy ky[jy] * tmp[b][y - jy + 8][x]
__global__ void __launch_bounds__(256) conv_y_kernel(const float* __restrict__ k2,
                                                     float* __restrict__ out)
{
    int i = blockIdx.x * blockDim.x + threadIdx.x;  // over NB*BOX*(BOX/4)
    if (i >= NB*BOX*(BOX/4)) return;
    int x4 = i % (BOX/4);
    int y  = (i / (BOX/4)) % BOX;
    int b  = i / ((BOX/4) * BOX);

    float inv_c = 1.f / k2[HALF*KS + HALF];
    const float4* tb = (const float4*)(g_tmp + (size_t)b * TROWS * BOX);
    float4 acc = make_float4(0.f, 0.f, 0.f, 0.f);
    #pragma unroll
    for (int jy = 0; jy < KS; jy++) {
        float ky = k2[jy*KS + HALF] * inv_c;   /* ky[jy] = k2[jy][4] / k2[4][4] */
        float4 v = tb[(y - jy + 2*HALF) * (BOX/4) + x4];
        acc.x += ky * v.x; acc.y += ky * v.y; acc.z += ky * v.z; acc.w += ky * v.w;
    }
    ((float4*)out)[i] = acc;
}

extern "C" void kernel_launch(void* const* d_in, const int* in_sizes, int n_in,
                              void* d_out, int out_size)
{
    const float* z          = (const float*)d_in[0];
    const float* r          = (const float*)d_in[1];
    const float* pos        = (const float*)d_in[2];
    const float* amp        = (const float*)d_in[3];
    const float* linamp1_W  = (const float*)d_in[4];
    const float* ampblock_W = (const float*)d_in[5];
    const float* ampblock_b = (const float*)d_in[6];
    const float* linamp2_W  = (const float*)d_in[7];
    const float* linamp2_b  = (const float*)d_in[8];
    const float* lin0_W     = (const float*)d_in[9];
    const float* deform_W   = (const float*)d_in[10];
    const float* deform_b   = (const float*)d_in[11];
    const float* lin1a_W    = (const float*)d_in[12];
    const float* lin1b_W    = (const float*)d_in[13];
    const float* k2         = (const float*)d_in[14];
    const int*   dptr       = (const int*)d_in[15];
    float* out = (float*)d_out;

    zero_tmp_kernel<<<(NB*TROWS*BOX/4 + 255)/256, 256>>>();
    fused_decoder_kernel<<<(NB*NP + 255)/256, 256>>>(
        z, r, pos, amp, linamp1_W, ampblock_W, ampblock_b, linamp2_W, linamp2_b,
        lin0_W, deform_W, deform_b, lin1a_W, lin1b_W, k2, dptr, out);
    conv_y_kernel<<<(NB*BOX*(BOX/4) + 255)/256, 256>>>(k2, out);
}

// round 4
// speedup vs baseline: 2.8005x; 1.1697x over previous
#include <cuda_runtime.h>

#define BOX 256
#define KS 9
#define HALF (KS/2)
#define NP 20000
#define NB 16
#define NN 32
#define NL 3
#define LATENT 8

#define TDIM (BOX + KS - 1)              /* 264: padded in both x and y */
#define IMG_SIZE (NB*BOX*BOX)            /* 1048576 */
#define OFF_PD   (IMG_SIZE)              /* 1048576 */
#define OFF_RES  (OFF_PD + NB*NP*3)      /* 2008576 */
#define OFF_AC   (OFF_RES + NB*NP*3)     /* 2968576 */

__device__ float g_tmp[NB * TDIM * TDIM];   /* 4.46 MB scratch: point-mass buffer */

typedef unsigned long long u64;

__device__ __forceinline__ u64 ffma2(u64 a, u64 b, u64 c) {
    u64 d;
    asm("fma.rn.f32x2 %0, %1, %2, %3;" : "=l"(d) : "l"(a), "l"(b), "l"(c));
    return d;
}
__device__ __forceinline__ u64 dup2(float v) {
    u64 d;
    asm("mov.b64 %0, {%1, %1};" : "=l"(d) : "f"(v));
    return d;
}
__device__ __forceinline__ float2 unpk(u64 a) {
    float2 d;
    asm("mov.b64 {%0, %1}, %2;" : "=f"(d.x), "=f"(d.y) : "l"(a));
    return d;
}

__global__ void zero_tmp_kernel(void) {
    int i = blockIdx.x * blockDim.x + threadIdx.x;
    if (i < NB*TDIM*TDIM/4) ((float4*)g_tmp)[i] = make_float4(0.f, 0.f, 0.f, 0.f);
}

__global__ void __launch_bounds__(256) fused_decoder_kernel(
    const float* __restrict__ z,          // [16,8]
    const float* __restrict__ r,          // [16,3,3]
    const float* __restrict__ pos,        // [20000,3]
    const float* __restrict__ amp,        // [1]
    const float* __restrict__ linamp1_W,  // [32,4]
    const float* __restrict__ ampblock_W, // [3,32,32]
    const float* __restrict__ ampblock_b, // [3,32]
    const float* __restrict__ linamp2_W,  // [1,32]
    const float* __restrict__ linamp2_b,  // [1]
    const float* __restrict__ lin0_W,     // [32,10]
    const float* __restrict__ deform_W,   // [3,32,32]
    const float* __restrict__ deform_b,   // [3,32]
    const float* __restrict__ lin1a_W,    // [3,32]
    const float* __restrict__ lin1b_W,    // [3,3]
    const int*   __restrict__ dptr,       // [1]
    float* __restrict__ out)
{
    // Weight matrices pre-interleaved as neuron-pairs: entry (l,p,j) = (W[l][2p][j], W[l][2p+1][j])
    __shared__ __align__(16) float2 s_ab_Wp[NL*16*NN];
    __shared__ __align__(16) float2 s_df_Wp[NL*16*NN];
    __shared__ __align__(16) float2 s_ab_bp[NL*16];
    __shared__ __align__(16) float2 s_df_bp[NL*16];
    __shared__ __align__(16) float2 s_la1p[16*4];
    __shared__ __align__(16) float2 s_l0p[16*10];
    __shared__ float s_la2[NN];
    __shared__ float s_l1a[3*NN];
    __shared__ float s_l1b[9];
    __shared__ float s_z[NB*LATENT];
    __shared__ float s_r[NB*9];
    __shared__ float s_la2b, s_amp;

    int tid = threadIdx.x;
    for (int i = tid; i < NL*16*NN; i += 256) {
        int j = i & 31, p = (i >> 5) & 15, l = i >> 9;
        s_ab_Wp[i] = make_float2(ampblock_W[(l*NN + 2*p)*NN + j], ampblock_W[(l*NN + 2*p+1)*NN + j]);
        s_df_Wp[i] = make_float2(deform_W  [(l*NN + 2*p)*NN + j], deform_W  [(l*NN + 2*p+1)*NN + j]);
    }
    for (int i = tid; i < NL*16; i += 256) {
        int p = i & 15, l = i >> 4;
        s_ab_bp[i] = make_float2(ampblock_b[l*NN + 2*p], ampblock_b[l*NN + 2*p+1]);
        s_df_bp[i] = make_float2(deform_b  [l*NN + 2*p], deform_b  [l*NN + 2*p+1]);
    }
    for (int i = tid; i < 16*4; i += 256) {
        int k = i & 3, p = i >> 2;
        s_la1p[i] = make_float2(linamp1_W[2*p*4 + k], linamp1_W[(2*p+1)*4 + k]);
    }
    for (int i = tid; i < 16*10; i += 256) {
        int k = i % 10, p = i / 10;
        s_l0p[i] = make_float2(lin0_W[2*p*10 + k], lin0_W[(2*p+1)*10 + k]);
    }
    for (int i = tid; i < NN; i += 256)       s_la2[i] = linamp2_W[i];
    for (int i = tid; i < 3*NN; i += 256)     s_l1a[i] = lin1a_W[i];
    for (int i = tid; i < 9; i += 256)        s_l1b[i] = lin1b_W[i];
    for (int i = tid; i < NB*LATENT; i += 256) s_z[i]  = z[i];
    for (int i = tid; i < NB*9; i += 256)      s_r[i]  = r[i];
    if (tid == 0) { s_la2b = linamp2_b[0]; s_amp = amp[0]; }
    __syncthreads();

    int idx = blockIdx.x * 256 + tid;   // grid exactly covers NB*NP
    int p = idx % NP;
    int b = idx / NP;
    int d = *dptr;

    float px = pos[3*p + 0];
    float py = pos[3*p + 1];
    float pz = pos[3*p + 2];

    float yv[NN];    // scalar activations (canonical)
    u64   xd[NN];    // dup-packed copies used as FFMA2 operands

    // ------------------ amplitude head ------------------
    {
        u64 dpx = dup2(px), dpy = dup2(py), dpz = dup2(pz), dzl = dup2(s_z[b*LATENT + 7]);
        #pragma unroll
        for (int pp = 0; pp < 16; pp++) {
            const ulonglong2* wr = (const ulonglong2*)&s_la1p[pp*4];
            ulonglong2 w01 = wr[0], w23 = wr[1];
            u64 acc = 0ULL;
            acc = ffma2(w01.x, dpx, acc);
            acc = ffma2(w01.y, dpy, acc);
            acc = ffma2(w23.x, dpz, acc);
            acc = ffma2(w23.y, dzl, acc);
            float2 a2 = unpk(acc);
            yv[2*pp] = a2.x; yv[2*pp+1] = a2.y;
        }
    }
    #pragma unroll
    for (int l = 0; l < NL; l++) {
        #pragma unroll
        for (int i = 0; i < NN; i++) xd[i] = dup2(yv[i]);
        const u64* bp = (const u64*)&s_ab_bp[l*16];
        #pragma unroll
        for (int pp = 0; pp < 16; pp++) {
            const ulonglong2* wr = (const ulonglong2*)&s_ab_Wp[(l*16 + pp)*NN];
            u64 acc = bp[pp];
            #pragma unroll
            for (int jj = 0; jj < 16; jj++) {
                ulonglong2 w = wr[jj];
                acc = ffma2(w.x, xd[2*jj],   acc);
                acc = ffma2(w.y, xd[2*jj+1], acc);
            }
            float2 a2 = unpk(acc);
            yv[2*pp]   = fmaxf(a2.x, 0.f) + yv[2*pp];
            yv[2*pp+1] = fmaxf(a2.y, 0.f) + yv[2*pp+1];
        }
    }
    float sacc = s_la2b;
    #pragma unroll
    for (int i = 0; i < NN; i++) sacc += yv[i]*s_la2[i];
    float amp_corr = 1.f / (1.f + expf(-sacc));

    // ------------------ deform head ------------------
    float res0 = 0.f, res1 = 0.f, res2 = 0.f;
    if (d > 0) {
        u64 din[10];
        din[0] = dup2(px); din[1] = dup2(py); din[2] = dup2(pz);
        #pragma unroll
        for (int j = 0; j < LATENT-1; j++) din[3+j] = dup2(s_z[b*LATENT + j]);
        #pragma unroll
        for (int pp = 0; pp < 16; pp++) {
            const ulonglong2* wr = (const ulonglong2*)&s_l0p[pp*10];
            u64 acc = 0ULL;
            #pragma unroll
            for (int kk = 0; kk < 5; kk++) {
                ulonglong2 w = wr[kk];
                acc = ffma2(w.x, din[2*kk],   acc);
                acc = ffma2(w.y, din[2*kk+1], acc);
            }
            float2 a2 = unpk(acc);
            yv[2*pp] = a2.x; yv[2*pp+1] = a2.y;
        }
        #pragma unroll
        for (int l = 0; l < NL; l++) {
            #pragma unroll
            for (int i = 0; i < NN; i++) xd[i] = dup2(yv[i]);
            const u64* bp = (const u64*)&s_df_bp[l*16];
            #pragma unroll
            for (int pp = 0; pp < 16; pp++) {
                const ulonglong2* wr = (const ulonglong2*)&s_df_Wp[(l*16 + pp)*NN];
                u64 acc = bp[pp];
                #pragma unroll
                for (int jj = 0; jj < 16; jj++) {
                    ulonglong2 w = wr[jj];
                    acc = ffma2(w.x, xd[2*jj],   acc);
                    acc = ffma2(w.y, xd[2*jj+1], acc);
                }
                float2 a2 = unpk(acc);
                yv[2*pp]   = fmaxf(a2.x, 0.f) + yv[2*pp];
                yv[2*pp+1] = fmaxf(a2.y, 0.f) + yv[2*pp+1];
            }
        }
        float t0 = 0.f, t1 = 0.f, t2 = 0.f;
        #pragma unroll
        for (int j = 0; j < NN; j++) {
            t0 += yv[j]*s_l1a[0*NN + j];
            t1 += yv[j]*s_l1a[1*NN + j];
            t2 += yv[j]*s_l1a[2*NN + j];
        }
        t0 = tanhf(t0); t1 = tanhf(t1); t2 = tanhf(t2);
        res0 = t0*s_l1b[0] + t1*s_l1b[1] + t2*s_l1b[2];
        res1 = t0*s_l1b[3] + t1*s_l1b[4] + t2*s_l1b[5];
        res2 = t0*s_l1b[6] + t1*s_l1b[7] + t2*s_l1b[8];
    }
    float pd0 = px + res0;
    float pd1 = py + res1;
    float pd2 = pz + res2;

    // ------------------ outputs (pos_def, res, amp_corr) ------------------
    out[OFF_AC + idx] = amp_corr;
    out[OFF_RES + 3*idx + 0] = res0;
    out[OFF_RES + 3*idx + 1] = res1;
    out[OFF_RES + 3*idx + 2] = res2;
    out[OFF_PD + 3*idx + 0] = pd0;
    out[OFF_PD + 3*idx + 1] = pd1;
    out[OFF_PD + 3*idx + 2] = pd2;

    // ------------------ project + point-mass scatter (1 atomic/point) ------------------
    const float* rb = &s_r[b*9];
    float proj0 = rb[0]*pd0 + rb[1]*pd1 + rb[2]*pd2;
    float proj1 = rb[3]*pd0 + rb[4]*pd1 + rb[5]*pd2;

    float A = s_amp * amp_corr;
    float fcx = rintf((proj0 + 0.5f) * (float)(BOX - 1));   // round-half-even, matches jnp.round
    float fcy = rintf((proj1 + 0.5f) * (float)(BOX - 1));

    if (fcx >= (float)(-HALF) && fcx <= (float)(BOX - 1 + HALF) &&
        fcy >= (float)(-HALF) && fcy <= (float)(BOX - 1 + HALF)) {
        int cx = (int)fcx, cy = (int)fcy;
        atomicAdd(&g_tmp[((size_t)b*TDIM + (cy + HALF))*TDIM + (cx + HALF)], A);
    }
}

// Dense separable 9x9 conv over padded point-mass buffer.
// out[b][y][x] = sum_jy ky[jy] * sum_jx kx[jx] * tmp[b][y+8-jy][x+8-jx]
// where kx[j] = k2[4][j], ky[j] = k2[j][4]/k2[4][4]  (exact outer-product factorization)
__global__ void __launch_bounds__(256) conv_sep_kernel(const float* __restrict__ k2,
                                                       float* __restrict__ out)
{
    __shared__ float s_in[72][72];    // 64+8 halo in both dims
    __shared__ float s_mid[72][64];

    int bt  = blockIdx.x;             // 16 batches x 4x4 tiles = 256 blocks
    int b   = bt >> 4;
    int ty0 = ((bt >> 2) & 3) * 64;
    int tx0 = (bt & 3) * 64;
    int tid = threadIdx.x;

    float inv_c = 1.f / k2[HALF*KS + HALF];
    float kx[KS], ky[KS];
    #pragma unroll
    for (int j = 0; j < KS; j++) { kx[j] = k2[HALF*KS + j]; ky[j] = k2[j*KS + HALF] * inv_c; }

    const float* base = g_tmp + ((size_t)b*TDIM + ty0)*TDIM + tx0;
    for (int i = tid; i < 72*72; i += 256) {
        int rr = i / 72, cc = i % 72;
        s_in[rr][cc] = base[rr*TDIM + cc];
    }
    __syncthreads();

    for (int i = tid; i < 72*64; i += 256) {
        int rr = i >> 6, x = i & 63;
        float a = 0.f;
        #pragma unroll
        for (int jx = 0; jx < KS; jx++) a += kx[jx] * s_in[rr][x + 2*HALF - jx];
        s_mid[rr][x] = a;
    }
    __syncthreads();

    for (int i = tid; i < 64*64; i += 256) {
        int y = i >> 6, x = i & 63;
        float a = 0.f;
        #pragma unroll
        for (int jy = 0; jy < KS; jy++) a += ky[jy] * s_mid[y + 2*HALF - jy][x];
        out[((size_t)b*BOX + ty0 + y)*BOX + tx0 + x] = a;
    }
}

extern "C" void kernel_launch(void* const* d_in, const int* in_sizes, int n_in,
                              void* d_out, int out_size)
{
    const float* z          = (const float*)d_in[0];
    const float* r          = (const float*)d_in[1];
    const float* pos        = (const float*)d_in[2];
    const float* amp        = (const float*)d_in[3];
    const float* linamp1_W  = (const float*)d_in[4];
    const float* ampblock_W = (const float*)d_in[5];
    const float* ampblock_b = (const float*)d_in[6];
    const float* linamp2_W  = (const float*)d_in[7];
    const float* linamp2_b  = (const float*)d_in[8];
    const float* lin0_W     = (const float*)d_in[9];
    const float* deform_W   = (const float*)d_in[10];
    const float* deform_b   = (const float*)d_in[11];
    const float* lin1a_W    = (const float*)d_in[12];
    const float* lin1b_W    = (const float*)d_in[13];
    const float* k2         = (const float*)d_in[14];
    const int*   dptr       = (const int*)d_in[15];
    float* out = (float*)d_out;

    zero_tmp_kernel<<<(NB*TDIM*TDIM/4 + 255)/256, 256>>>();
    fused_decoder_kernel<<<(NB*NP)/256, 256>>>(
        z, r, pos, amp, linamp1_W, ampblock_W, ampblock_b, linamp2_W, linamp2_b,
        lin0_W, deform_W, deform_b, lin1a_W, lin1b_W, dptr, out);
    conv_sep_kernel<<<256, 256>>>(k2, out);
}

// round 5
// speedup vs baseline: 3.3464x; 1.1949x over previous
#include <cuda_runtime.h>

#define BOX 256
#define KS 9
#define HALF (KS/2)
#define NP 20000
#define NB 16
#define NN 32
#define NL 3
#define LATENT 8

#define TDIM (BOX + KS - 1)              /* 264: padded in both x and y */
#define IMG_SIZE (NB*BOX*BOX)            /* 1048576 */
#define OFF_PD   (IMG_SIZE)              /* 1048576 */
#define OFF_RES  (OFF_PD + NB*NP*3)      /* 2008576 */
#define OFF_AC   (OFF_RES + NB*NP*3)     /* 2968576 */

__device__ float g_tmp[NB * TDIM * TDIM];   /* 4.46 MB scratch: point-mass buffer */

typedef unsigned long long u64;

__device__ __forceinline__ u64 ffma2(u64 a, u64 b, u64 c) {
    u64 d;
    asm("fma.rn.f32x2 %0, %1, %2, %3;" : "=l"(d) : "l"(a), "l"(b), "l"(c));
    return d;
}
__device__ __forceinline__ u64 dup2(float v) {
    u64 d;
    asm("mov.b64 %0, {%1, %1};" : "=l"(d) : "f"(v));
    return d;
}
__device__ __forceinline__ float2 unpk(u64 a) {
    float2 d;
    asm("mov.b64 {%0, %1}, %2;" : "=f"(d.x), "=f"(d.y) : "l"(a));
    return d;
}
__device__ __forceinline__ u64 pk2(float a, float b) {
    u64 d;
    asm("mov.b64 %0, {%1, %2};" : "=l"(d) : "f"(a), "f"(b));
    return d;
}
__device__ __forceinline__ float tanh_fast(float x) {
    float e = __expf(2.f * x);
    return 1.f - __fdividef(2.f, e + 1.f);
}
__device__ __forceinline__ float sigmoid_fast(float x) {
    return __fdividef(1.f, 1.f + __expf(-x));
}

__global__ void zero_tmp_kernel(void) {
    int i = blockIdx.x * blockDim.x + threadIdx.x;
    if (i < NB*TDIM*TDIM/4) ((float4*)g_tmp)[i] = make_float4(0.f, 0.f, 0.f, 0.f);
}

__global__ void __launch_bounds__(256, 2) fused_decoder_kernel(
    const float* __restrict__ z,          // [16,8]
    const float* __restrict__ r,          // [16,3,3]
    const float* __restrict__ pos,        // [20000,3]
    const float* __restrict__ amp,        // [1]
    const float* __restrict__ linamp1_W,  // [32,4]
    const float* __restrict__ ampblock_W, // [3,32,32]
    const float* __restrict__ ampblock_b, // [3,32]
    const float* __restrict__ linamp2_W,  // [1,32]
    const float* __restrict__ linamp2_b,  // [1]
    const float* __restrict__ lin0_W,     // [32,10]
    const float* __restrict__ deform_W,   // [3,32,32]
    const float* __restrict__ deform_b,   // [3,32]
    const float* __restrict__ lin1a_W,    // [3,32]
    const float* __restrict__ lin1b_W,    // [3,3]
    const int*   __restrict__ dptr,       // [1]
    float* __restrict__ out)
{
    // Weights pre-interleaved as neuron pairs: s_*_Wp[((l*16+pp)*32 + j)] = (W[l][2pp][j], W[l][2pp+1][j])
    __shared__ __align__(16) float2 s_ab_Wp[NL*16*NN];
    __shared__ __align__(16) float2 s_df_Wp[NL*16*NN];
    __shared__ __align__(16) float2 s_ab_bp[NL*16];
    __shared__ __align__(16) float2 s_df_bp[NL*16];
    __shared__ __align__(16) float2 s_la1p[16*3];    // pos weights only (j=0..2), pair-packed
    __shared__ __align__(16) float2 s_l0p[16*3];     // pos weights only
    __shared__ __align__(16) float2 s_camp[NB*16];   // per-batch latent contribution, amp head
    __shared__ __align__(16) float2 s_cdef[NB*16];   // per-batch latent contribution, deform head
    __shared__ float s_la2[NN];
    __shared__ float s_l1a[3*NN];
    __shared__ float s_l1b[9];
    __shared__ float s_r[NB*9];
    __shared__ float s_la2b, s_amp;

    int tid = threadIdx.x;
    for (int i = tid; i < NL*16*NN; i += 256) {
        int j = i & 31, pp = (i >> 5) & 15, l = i >> 9;
        s_ab_Wp[i] = make_float2(ampblock_W[(l*NN + 2*pp)*NN + j], ampblock_W[(l*NN + 2*pp+1)*NN + j]);
        s_df_Wp[i] = make_float2(deform_W  [(l*NN + 2*pp)*NN + j], deform_W  [(l*NN + 2*pp+1)*NN + j]);
    }
    for (int i = tid; i < NL*16; i += 256) {
        int pp = i & 15, l = i >> 4;
        s_ab_bp[i] = make_float2(ampblock_b[l*NN + 2*pp], ampblock_b[l*NN + 2*pp+1]);
        s_df_bp[i] = make_float2(deform_b  [l*NN + 2*pp], deform_b  [l*NN + 2*pp+1]);
    }
    for (int i = tid; i < 16*3; i += 256) {
        int k = i % 3, pp = i / 3;
        s_la1p[pp*3 + k] = make_float2(linamp1_W[2*pp*4 + k],  linamp1_W[(2*pp+1)*4 + k]);
        s_l0p [pp*3 + k] = make_float2(lin0_W  [2*pp*10 + k],  lin0_W  [(2*pp+1)*10 + k]);
    }
    // per-batch latent precompute: c_amp[b][i] = W_la1[i][3]*z[b][7];
    //                              c_def[b][i] = sum_{j=0..6} W_l0[i][3+j]*z[b][j]
    for (int i = tid; i < NB*NN; i += 256) {
        int n = i & 31, b = i >> 5;
        ((float*)s_camp)[b*NN + n] = linamp1_W[n*4 + 3] * z[b*LATENT + 7];
        float c = 0.f;
        #pragma unroll
        for (int j = 0; j < LATENT-1; j++) c += lin0_W[n*10 + 3 + j] * z[b*LATENT + j];
        ((float*)s_cdef)[b*NN + n] = c;
    }
    for (int i = tid; i < NN; i += 256)     s_la2[i] = linamp2_W[i];
    for (int i = tid; i < 3*NN; i += 256)   s_l1a[i] = lin1a_W[i];
    for (int i = tid; i < 9; i += 256)      s_l1b[i] = lin1b_W[i];
    for (int i = tid; i < NB*9; i += 256)   s_r[i]  = r[i];
    if (tid == 0) { s_la2b = linamp2_b[0]; s_amp = amp[0]; }
    __syncthreads();

    int idx = blockIdx.x * 256 + tid;   // grid exactly covers NB*NP
    int p = idx % NP;
    int b = idx / NP;
    int d = *dptr;

    float px = pos[3*p + 0];
    float py = pos[3*p + 1];
    float pz = pos[3*p + 2];

    float xs[NN];     // scalar activations
    u64   acc2[16];   // packed neuron-pair accumulators

    // ------------------ amplitude head ------------------
    {
        u64 dpx = dup2(px), dpy = dup2(py), dpz = dup2(pz);
        const u64* cb = (const u64*)&s_camp[b*16];
        #pragma unroll
        for (int pp = 0; pp < 16; pp++) {
            u64 a = cb[pp];
            a = ffma2(*(const u64*)&s_la1p[pp*3 + 0], dpx, a);
            a = ffma2(*(const u64*)&s_la1p[pp*3 + 1], dpy, a);
            a = ffma2(*(const u64*)&s_la1p[pp*3 + 2], dpz, a);
            float2 a2 = unpk(a);
            xs[2*pp] = a2.x; xs[2*pp+1] = a2.y;
        }
    }
    #pragma unroll
    for (int l = 0; l < NL; l++) {
        const u64* bp = (const u64*)&s_ab_bp[l*16];
        #pragma unroll
        for (int pp = 0; pp < 16; pp++) acc2[pp] = bp[pp];
        #pragma unroll
        for (int j2 = 0; j2 < 16; j2++) {
            u64 da = dup2(xs[2*j2]);
            u64 db = dup2(xs[2*j2+1]);
            const ulonglong2* col = (const ulonglong2*)&s_ab_Wp[l*16*NN + 2*j2];
            #pragma unroll
            for (int pp = 0; pp < 16; pp++) {
                ulonglong2 w = col[pp*16];   // = &s_ab_Wp[(l*16+pp)*NN + 2*j2]
                acc2[pp] = ffma2(w.x, da, acc2[pp]);
                acc2[pp] = ffma2(w.y, db, acc2[pp]);
            }
        }
        #pragma unroll
        for (int pp = 0; pp < 16; pp++) {
            float2 a2 = unpk(acc2[pp]);
            xs[2*pp]   += fmaxf(a2.x, 0.f);
            xs[2*pp+1] += fmaxf(a2.y, 0.f);
        }
    }
    float sacc = s_la2b;
    #pragma unroll
    for (int i = 0; i < NN; i++) sacc += xs[i]*s_la2[i];
    float amp_corr = sigmoid_fast(sacc);

    // ------------------ deform head ------------------
    float res0 = 0.f, res1 = 0.f, res2 = 0.f;
    if (d > 0) {
        u64 dpx = dup2(px), dpy = dup2(py), dpz = dup2(pz);
        const u64* cb = (const u64*)&s_cdef[b*16];
        #pragma unroll
        for (int pp = 0; pp < 16; pp++) {
            u64 a = cb[pp];
            a = ffma2(*(const u64*)&s_l0p[pp*3 + 0], dpx, a);
            a = ffma2(*(const u64*)&s_l0p[pp*3 + 1], dpy, a);
            a = ffma2(*(const u64*)&s_l0p[pp*3 + 2], dpz, a);
            float2 a2 = unpk(a);
            xs[2*pp] = a2.x; xs[2*pp+1] = a2.y;
        }
        #pragma unroll
        for (int l = 0; l < NL; l++) {
            const u64* bp = (const u64*)&s_df_bp[l*16];
            #pragma unroll
            for (int pp = 0; pp < 16; pp++) acc2[pp] = bp[pp];
            #pragma unroll
            for (int j2 = 0; j2 < 16; j2++) {
                u64 da = dup2(xs[2*j2]);
                u64 db = dup2(xs[2*j2+1]);
                const ulonglong2* col = (const ulonglong2*)&s_df_Wp[l*16*NN + 2*j2];
                #pragma unroll
                for (int pp = 0; pp < 16; pp++) {
                    ulonglong2 w = col[pp*16];
                    acc2[pp] = ffma2(w.x, da, acc2[pp]);
                    acc2[pp] = ffma2(w.y, db, acc2[pp]);
                }
            }
            #pragma unroll
            for (int pp = 0; pp < 16; pp++) {
                float2 a2 = unpk(acc2[pp]);
                xs[2*pp]   += fmaxf(a2.x, 0.f);
                xs[2*pp+1] += fmaxf(a2.y, 0.f);
            }
        }
        float t0 = 0.f, t1 = 0.f, t2 = 0.f;
        #pragma unroll
        for (int j = 0; j < NN; j++) {
            t0 += xs[j]*s_l1a[0*NN + j];
            t1 += xs[j]*s_l1a[1*NN + j];
            t2 += xs[j]*s_l1a[2*NN + j];
        }
        t0 = tanh_fast(t0); t1 = tanh_fast(t1); t2 = tanh_fast(t2);
        res0 = t0*s_l1b[0] + t1*s_l1b[1] + t2*s_l1b[2];
        res1 = t0*s_l1b[3] + t1*s_l1b[4] + t2*s_l1b[5];
        res2 = t0*s_l1b[6] + t1*s_l1b[7] + t2*s_l1b[8];
    }
    float pd0 = px + res0;
    float pd1 = py + res1;
    float pd2 = pz + res2;

    // ------------------ outputs (pos_def, res, amp_corr) ------------------
    out[OFF_AC + idx] = amp_corr;
    out[OFF_RES + 3*idx + 0] = res0;
    out[OFF_RES + 3*idx + 1] = res1;
    out[OFF_RES + 3*idx + 2] = res2;
    out[OFF_PD + 3*idx + 0] = pd0;
    out[OFF_PD + 3*idx + 1] = pd1;
    out[OFF_PD + 3*idx + 2] = pd2;

    // ------------------ project + point-mass scatter (1 atomic/point) ------------------
    const float* rb = &s_r[b*9];
    float proj0 = rb[0]*pd0 + rb[1]*pd1 + rb[2]*pd2;
    float proj1 = rb[3]*pd0 + rb[4]*pd1 + rb[5]*pd2;

    float A = s_amp * amp_corr;
    float fcx = rintf((proj0 + 0.5f) * (float)(BOX - 1));   // round-half-even, matches jnp.round
    float fcy = rintf((proj1 + 0.5f) * (float)(BOX - 1));

    if (fcx >= (float)(-HALF) && fcx <= (float)(BOX - 1 + HALF) &&
        fcy >= (float)(-HALF) && fcy <= (float)(BOX - 1 + HALF)) {
        int cx = (int)fcx, cy = (int)fcy;
        atomicAdd(&g_tmp[((size_t)b*TDIM + (cy + HALF))*TDIM + (cx + HALF)], A);
    }
}

// Dense separable 9x9 conv over padded point-mass buffer.
// out[b][y][x] = sum_jy ky[jy] * sum_jx kx[jx] * tmp[b][y+8-jy][x+8-jx]
// where kx[j] = k2[4][j], ky[j] = k2[j][4]/k2[4][4]  (exact outer-product factorization)
__global__ void __launch_bounds__(256) conv_sep_kernel(const float* __restrict__ k2,
                                                       float* __restrict__ out)
{
    __shared__ float s_in[72][72];    // 64+8 halo in both dims
    __shared__ float s_mid[72][64];

    int bt  = blockIdx.x;             // 16 batches x 4x4 tiles = 256 blocks
    int b   = bt >> 4;
    int ty0 = ((bt >> 2) & 3) * 64;
    int tx0 = (bt & 3) * 64;
    int tid = threadIdx.x;

    float inv_c = 1.f / k2[HALF*KS + HALF];
    float kx[KS], ky[KS];
    #pragma unroll
    for (int j = 0; j < KS; j++) { kx[j] = k2[HALF*KS + j]; ky[j] = k2[j*KS + HALF] * inv_c; }

    const float* base = g_tmp + ((size_t)b*TDIM + ty0)*TDIM + tx0;
    for (int i = tid; i < 72*72; i += 256) {
        int rr = i / 72, cc = i % 72;
        s_in[rr][cc] = base[rr*TDIM + cc];
    }
    __syncthreads();

    for (int i = tid; i < 72*64; i += 256) {
        int rr = i >> 6, x = i & 63;
        float a = 0.f;
        #pragma unroll
        for (int jx = 0; jx < KS; jx++) a += kx[jx] * s_in[rr][x + 2*HALF - jx];
        s_mid[rr][x] = a;
    }
    __syncthreads();

    for (int i = tid; i < 64*64; i += 256) {
        int y = i >> 6, x = i & 63;
        float a = 0.f;
        #pragma unroll
        for (int jy = 0; jy < KS; jy++) a += ky[jy] * s_mid[y + 2*HALF - jy][x];
        out[((size_t)b*BOX + ty0 + y)*BOX + tx0 + x] = a;
    }
}

extern "C" void kernel_launch(void* const* d_in, const int* in_sizes, int n_in,
                              void* d_out, int out_size)
{
    const float* z          = (const float*)d_in[0];
    const float* r          = (const float*)d_in[1];
    const float* pos        = (const float*)d_in[2];
    const float* amp        = (const float*)d_in[3];
    const float* linamp1_W  = (const float*)d_in[4];
    const float* ampblock_W = (const float*)d_in[5];
    const float* ampblock_b = (const float*)d_in[6];
    const float* linamp2_W  = (const float*)d_in[7];
    const float* linamp2_b  = (const float*)d_in[8];
    const float* lin0_W     = (const float*)d_in[9];
    const float* deform_W   = (const float*)d_in[10];
    const float* deform_b   = (const float*)d_in[11];
    const float* lin1a_W    = (const float*)d_in[12];
    const float* lin1b_W    = (const float*)d_in[13];
    const float* k2         = (const float*)d_in[14];
    const int*   dptr       = (const int*)d_in[15];
    float* out = (float*)d_out;

    zero_tmp_kernel<<<(NB*TDIM*TDIM/4 + 255)/256, 256>>>();
    fused_decoder_kernel<<<(NB*NP)/256, 256>>>(
        z, r, pos, amp, linamp1_W, ampblock_W, ampblock_b, linamp2_W, linamp2_b,
        lin0_W, deform_W, deform_b, lin1a_W, lin1b_W, dptr, out);
    conv_sep_kernel<<<256, 256>>>(k2, out);
}